// round 1
// baseline (speedup 1.0000x reference)
#include <cuda_runtime.h>
#include <math.h>

#define BATCH 2
#define SEQ   2048
#define EMB   1024
#define HEADS 16
#define DHEAD 64
#define MROWS (BATCH*SEQ)        // 4096

// ---------------- scratch (static device globals; no allocation) -------------
__device__ float g_Wk [EMB*EMB];     // [h*64+d][k] gathered from Wqkv rows d*48+16+h
__device__ float g_Wv [EMB*EMB];     // rows d*48+32+h
__device__ float g_Wtq[EMB*EMB];     // from Wtqkv rows d*48+0+h
__device__ float g_K  [MROWS*EMB];   // K  in layout [b*T+t][h*64+d]
__device__ float g_V  [MROWS*EMB];
__device__ float g_TQ [MROWS*EMB];
__device__ float g_O  [MROWS*EMB];   // attention output, layout 'b t (h d)'

// ---------------- weight permutation ----------------------------------------
// out row n = h*64+d  <-  Wqkv row d*48 + koff + h
__global__ void permute_w_kernel(const float* __restrict__ Wqkv,
                                 const float* __restrict__ Wtqkv)
{
    int k = blockIdx.x * 256 + threadIdx.x;   // 0..1023
    int n = blockIdx.y;                        // 0..1023
    int h = n >> 6;
    int d = n & 63;
    size_t dst = (size_t)n * EMB + k;
    g_Wk [dst] = Wqkv [(size_t)(d*48 + 16 + h) * EMB + k];
    g_Wv [dst] = Wqkv [(size_t)(d*48 + 32 + h) * EMB + k];
    g_Wtq[dst] = Wtqkv[(size_t)(d*48 +  0 + h) * EMB + k];
}

// ---------------- tiled SGEMM: C[M,N] = A[M,K] * B[N,K]^T --------------------
#define BM 128
#define BN 128
#define BK 16

__global__ __launch_bounds__(256)
void sgemm_nt(const float* __restrict__ A, const float* __restrict__ B,
              float* __restrict__ C, int M, int N, int K)
{
    __shared__ float As[BK][BM];
    __shared__ float Bs[BK][BN];

    const int tid = threadIdx.x;
    const int tm  = tid >> 4;            // 0..15
    const int tn  = tid & 15;            // 0..15
    const int rowBase = blockIdx.y * BM;
    const int colBase = blockIdx.x * BN;

    const int ldRow = tid >> 2;          // 0..63
    const int ldCol = (tid & 3) << 2;    // 0,4,8,12

    float acc[8][8];
    #pragma unroll
    for (int i = 0; i < 8; i++)
        #pragma unroll
        for (int j = 0; j < 8; j++) acc[i][j] = 0.f;

    for (int k0 = 0; k0 < K; k0 += BK) {
        #pragma unroll
        for (int p = 0; p < 2; p++) {
            int r = p * 64 + ldRow;
            float4 a = *(const float4*)(A + (size_t)(rowBase + r) * K + k0 + ldCol);
            As[ldCol+0][r] = a.x; As[ldCol+1][r] = a.y;
            As[ldCol+2][r] = a.z; As[ldCol+3][r] = a.w;
            float4 b = *(const float4*)(B + (size_t)(colBase + r) * K + k0 + ldCol);
            Bs[ldCol+0][r] = b.x; Bs[ldCol+1][r] = b.y;
            Bs[ldCol+2][r] = b.z; Bs[ldCol+3][r] = b.w;
        }
        __syncthreads();

        #pragma unroll
        for (int kk = 0; kk < BK; kk++) {
            float a[8], b[8];
            *(float4*)&a[0] = *(const float4*)&As[kk][tm*8];
            *(float4*)&a[4] = *(const float4*)&As[kk][tm*8+4];
            *(float4*)&b[0] = *(const float4*)&Bs[kk][tn*8];
            *(float4*)&b[4] = *(const float4*)&Bs[kk][tn*8+4];
            #pragma unroll
            for (int i = 0; i < 8; i++)
                #pragma unroll
                for (int j = 0; j < 8; j++)
                    acc[i][j] += a[i] * b[j];
        }
        __syncthreads();
    }

    #pragma unroll
    for (int i = 0; i < 8; i++) {
        size_t r = (size_t)(rowBase + tm*8 + i);
        float4 c0 = make_float4(acc[i][0], acc[i][1], acc[i][2], acc[i][3]);
        float4 c1 = make_float4(acc[i][4], acc[i][5], acc[i][6], acc[i][7]);
        *(float4*)(C + r * N + colBase + tn*8)     = c0;
        *(float4*)(C + r * N + colBase + tn*8 + 4) = c1;
    }
}

// ---------------- flash attention (fp32, 1 thread = 1 query row) -------------
// grid: (SEQ/128, HEADS, BATCH), block: 128 threads
__global__ __launch_bounds__(128)
void attn_kernel()
{
    const int qi = blockIdx.x * 128 + threadIdx.x;   // query position in t
    const int h  = blockIdx.y;
    const int b  = blockIdx.z;

    __shared__ float Ks[64][64];
    __shared__ float Vs[64][64];

    float q[64];
    const float* qrow = g_TQ + ((size_t)(b*SEQ + qi)) * EMB + h*DHEAD;
    #pragma unroll
    for (int i = 0; i < 16; i++) {
        float4 v4 = *(const float4*)(qrow + i*4);
        q[i*4+0] = v4.x; q[i*4+1] = v4.y; q[i*4+2] = v4.z; q[i*4+3] = v4.w;
    }

    float o[64];
    #pragma unroll
    for (int i = 0; i < 64; i++) o[i] = 0.f;
    float mmax = -INFINITY, l = 0.f;

    for (int jt = 0; jt < SEQ/64; jt++) {
        __syncthreads();
        // cooperative load of K/V tiles (64 rows x 64 cols each)
        #pragma unroll
        for (int it = 0; it < 8; it++) {
            int idx = it * 128 + threadIdx.x;        // 0..1023 float4 slots
            int r  = idx >> 4;
            int c4 = (idx & 15) << 2;
            size_t goff = ((size_t)(b*SEQ + jt*64 + r)) * EMB + h*DHEAD + c4;
            *(float4*)&Ks[r][c4] = *(const float4*)(g_K + goff);
            *(float4*)&Vs[r][c4] = *(const float4*)(g_V + goff);
        }
        __syncthreads();

        #pragma unroll
        for (int jc = 0; jc < 64; jc += 16) {
            float s[16];
            #pragma unroll
            for (int jj = 0; jj < 16; jj++) {
                float acc = 0.f;
                #pragma unroll
                for (int dd = 0; dd < 64; dd += 4) {
                    float4 kv = *(const float4*)&Ks[jc+jj][dd];
                    acc += q[dd]*kv.x + q[dd+1]*kv.y + q[dd+2]*kv.z + q[dd+3]*kv.w;
                }
                s[jj] = acc * 8.0f;   // * sqrt(d_head)
            }
            float cmax = s[0];
            #pragma unroll
            for (int jj = 1; jj < 16; jj++) cmax = fmaxf(cmax, s[jj]);
            float mnew = fmaxf(mmax, cmax);
            float corr = __expf(mmax - mnew);
            l *= corr;
            #pragma unroll
            for (int dd = 0; dd < 64; dd++) o[dd] *= corr;
            #pragma unroll
            for (int jj = 0; jj < 16; jj++) {
                float p = __expf(s[jj] - mnew);
                l += p;
                #pragma unroll
                for (int dd = 0; dd < 64; dd += 4) {
                    float4 vv = *(const float4*)&Vs[jc+jj][dd];
                    o[dd+0] += p * vv.x; o[dd+1] += p * vv.y;
                    o[dd+2] += p * vv.z; o[dd+3] += p * vv.w;
                }
            }
            mmax = mnew;
        }
    }

    float inv = 1.0f / l;
    float* orow = g_O + ((size_t)(b*SEQ + qi)) * EMB + h*DHEAD;
    #pragma unroll
    for (int dd = 0; dd < 64; dd += 4) {
        float4 ov = make_float4(o[dd]*inv, o[dd+1]*inv, o[dd+2]*inv, o[dd+3]*inv);
        *(float4*)(orow + dd) = ov;
    }
}

// ---------------- launch ------------------------------------------------------
extern "C" void kernel_launch(void* const* d_in, const int* in_sizes, int n_in,
                              void* d_out, int out_size)
{
    const float* x     = (const float*)d_in[0];
    const float* tx    = (const float*)d_in[1];
    const float* Wqkv  = (const float*)d_in[2];
    const float* Wtqkv = (const float*)d_in[3];
    const float* Wout  = (const float*)d_in[4];
    float* out = (float*)d_out;

    float *pWk, *pWv, *pWtq, *pK, *pV, *pTQ, *pO;
    cudaGetSymbolAddress((void**)&pWk,  g_Wk);
    cudaGetSymbolAddress((void**)&pWv,  g_Wv);
    cudaGetSymbolAddress((void**)&pWtq, g_Wtq);
    cudaGetSymbolAddress((void**)&pK,   g_K);
    cudaGetSymbolAddress((void**)&pV,   g_V);
    cudaGetSymbolAddress((void**)&pTQ,  g_TQ);
    cudaGetSymbolAddress((void**)&pO,   g_O);

    permute_w_kernel<<<dim3(EMB/256, EMB), 256>>>(Wqkv, Wtqkv);

    dim3 gemmGrid(EMB/BN, MROWS/BM);   // (8, 32)
    sgemm_nt<<<gemmGrid, 256>>>(x,  pWk,  pK,  MROWS, EMB, EMB);
    sgemm_nt<<<gemmGrid, 256>>>(x,  pWv,  pV,  MROWS, EMB, EMB);
    sgemm_nt<<<gemmGrid, 256>>>(tx, pWtq, pTQ, MROWS, EMB, EMB);

    attn_kernel<<<dim3(SEQ/128, HEADS, BATCH), 128>>>();

    sgemm_nt<<<gemmGrid, 256>>>(pO, Wout, out, MROWS, EMB, EMB);
}

// round 3
// speedup vs baseline: 3.4469x; 3.4469x over previous
#include <cuda_runtime.h>
#include <cuda_bf16.h>
#include <math.h>
#include <stdint.h>

#define BATCH 2
#define SEQ   2048
#define EMB   1024
#define HEADS 16
#define DHEAD 64
#define MROWS (BATCH*SEQ)         // 4096
#define NSLICE (BATCH*HEADS)      // 32

// ---------------- scratch (static device globals; no allocation) -------------
__device__ __nv_bfloat16 g_xh [MROWS*EMB], g_xl [MROWS*EMB];
__device__ __nv_bfloat16 g_txh[MROWS*EMB], g_txl[MROWS*EMB];
__device__ __nv_bfloat16 g_Kh [MROWS*EMB], g_Kl [MROWS*EMB];
__device__ __nv_bfloat16 g_TQh[MROWS*EMB], g_TQl[MROWS*EMB];
__device__ float         g_V  [MROWS*EMB];
__device__ __nv_bfloat16 g_Vth[NSLICE*DHEAD*SEQ], g_Vtl[NSLICE*DHEAD*SEQ];
__device__ __nv_bfloat16 g_Oh [MROWS*EMB], g_Ol [MROWS*EMB];
__device__ __nv_bfloat16 g_Wkh [EMB*EMB], g_Wkl [EMB*EMB];
__device__ __nv_bfloat16 g_Wvh [EMB*EMB], g_Wvl [EMB*EMB];
__device__ __nv_bfloat16 g_Wtqh[EMB*EMB], g_Wtql[EMB*EMB];
__device__ __nv_bfloat16 g_Wouth[EMB*EMB], g_Woutl[EMB*EMB];
__device__ float         g_E [(size_t)NSLICE*SEQ*SEQ];            // 536 MB
__device__ __nv_bfloat16 g_Ph[(size_t)NSLICE*SEQ*SEQ];            // 268 MB
__device__ __nv_bfloat16 g_Pl[(size_t)NSLICE*SEQ*SEQ];            // 268 MB

// ---------------- small helpers ----------------------------------------------
__device__ __forceinline__ uint32_t smem_u32(const void* p) {
    uint32_t a;
    asm("{ .reg .u64 t; cvta.to.shared.u64 t, %1; cvt.u32.u64 %0, t; }" : "=r"(a) : "l"(p));
    return a;
}
#define CP_ASYNC16(dst, src) \
    asm volatile("cp.async.cg.shared.global [%0], [%1], 16;" :: "r"(dst), "l"(src) : "memory")
#define CP_COMMIT() asm volatile("cp.async.commit_group;" ::: "memory")
#define CP_WAIT2()  asm volatile("cp.async.wait_group 2;" ::: "memory")

__device__ __forceinline__ void ldsm_x4(uint32_t r[4], uint32_t addr) {
    asm volatile("ldmatrix.sync.aligned.m8n8.x4.shared.b16 {%0,%1,%2,%3}, [%4];"
                 : "=r"(r[0]), "=r"(r[1]), "=r"(r[2]), "=r"(r[3]) : "r"(addr));
}
__device__ __forceinline__ void mma16816(float c[4], const uint32_t a[4],
                                         uint32_t b0, uint32_t b1) {
    asm volatile("mma.sync.aligned.m16n8k16.row.col.f32.bf16.bf16.f32 "
                 "{%0,%1,%2,%3},{%4,%5,%6,%7},{%8,%9},{%0,%1,%2,%3};"
                 : "+f"(c[0]), "+f"(c[1]), "+f"(c[2]), "+f"(c[3])
                 : "r"(a[0]), "r"(a[1]), "r"(a[2]), "r"(a[3]), "r"(b0), "r"(b1));
}
__device__ __forceinline__ uint32_t pack2(__nv_bfloat16 a, __nv_bfloat16 b) {
    return (uint32_t)__bfloat16_as_ushort(a) | ((uint32_t)__bfloat16_as_ushort(b) << 16);
}
__device__ __forceinline__ void split2(float x, __nv_bfloat16& h, __nv_bfloat16& l) {
    h = __float2bfloat16(x);
    l = __float2bfloat16(x - __bfloat162float(h));
}

// smem tile: rows x 32 halves, row stride 80 B (conflict-free for ldmatrix)
#define SSTR 80
#define A_BYTES (128*SSTR)   // 10240

// fill `rows` rows of 64B each from src (row stride ld halves) into smem
__device__ __forceinline__ void fill_rows(uint32_t dst, const __nv_bfloat16* src,
                                          int ld, int rows, int tid) {
    for (int j = tid; j < rows * 4; j += 256) {
        int r = j >> 2, cc = j & 3;
        CP_ASYNC16(dst + r * SSTR + cc * 16, src + (size_t)r * ld + cc * 8);
    }
}

// warp-level compute over one stage: MT m16-tiles, NP pairs of n8-tiles, BK=32
template<int MT, int NP>
__device__ __forceinline__ void compute_stage(uint32_t abase, uint32_t bbase,
                                              int wrow, int wcol, int lane,
                                              float (*cfr)[4]) {
    const int arow  = wrow + (lane & 15);
    const int acolh = (lane >> 4) * 8;
    const int brow  = wcol + (lane & 7) + ((lane >> 4) << 3);
    const int bcolh = ((lane >> 3) & 1) * 8;
#pragma unroll
    for (int ks = 0; ks < 2; ks++) {
        uint32_t a[MT][4], b[NP][4];
#pragma unroll
        for (int mt = 0; mt < MT; mt++)
            ldsm_x4(a[mt], abase + (uint32_t)(arow + mt * 16) * SSTR + (acolh + ks * 16) * 2);
#pragma unroll
        for (int np = 0; np < NP; np++)
            ldsm_x4(b[np], bbase + (uint32_t)(brow + np * 16) * SSTR + (bcolh + ks * 16) * 2);
#pragma unroll
        for (int mt = 0; mt < MT; mt++)
#pragma unroll
            for (int np = 0; np < NP; np++) {
                mma16816(cfr[(mt * NP + np) * 2 + 0], a[mt], b[np][0], b[np][1]);
                mma16816(cfr[(mt * NP + np) * 2 + 1], a[mt], b[np][2], b[np][3]);
            }
    }
}

// ---------------- conversion kernels -----------------------------------------
__global__ void split_convert(const float* __restrict__ X,
                              __nv_bfloat16* __restrict__ H,
                              __nv_bfloat16* __restrict__ L, int n)
{
    int i = blockIdx.x * blockDim.x + threadIdx.x;
    if (i >= n / 4) return;
    float4 v = ((const float4*)X)[i];
    __nv_bfloat16 h0, h1, h2, h3, l0, l1, l2, l3;
    split2(v.x, h0, l0); split2(v.y, h1, l1);
    split2(v.z, h2, l2); split2(v.w, h3, l3);
    ((uint2*)H)[i] = make_uint2(pack2(h0, h1), pack2(h2, h3));
    ((uint2*)L)[i] = make_uint2(pack2(l0, l1), pack2(l2, l3));
}

__global__ void permute_split_w(const float* __restrict__ Wqkv,
                                const float* __restrict__ Wtqkv)
{
    int k = blockIdx.x * 256 + threadIdx.x;
    int n = blockIdx.y;
    int h = n >> 6, d = n & 63;
    size_t dst = (size_t)n * EMB + k;
    float vk  = Wqkv [(size_t)(d * 48 + 16 + h) * EMB + k];
    float vv  = Wqkv [(size_t)(d * 48 + 32 + h) * EMB + k];
    float vtq = Wtqkv[(size_t)(d * 48 +  0 + h) * EMB + k];
    __nv_bfloat16 hh, ll;
    split2(vk,  hh, ll); g_Wkh [dst] = hh; g_Wkl [dst] = ll;
    split2(vv,  hh, ll); g_Wvh [dst] = hh; g_Wvl [dst] = ll;
    split2(vtq, hh, ll); g_Wtqh[dst] = hh; g_Wtql[dst] = ll;
}

// ---------------- projection / output GEMM -----------------------------------
// C[4096,1024] = A[4096,1024] * B[1024,1024]^T, 3-term split, BM=BN=128 BK=32
// MODE 0: write fp32 C; MODE 1: write bf16 split H/L
#define PROJ_CHUNKS 96
#define STAGE_PROJ (A_BYTES + 128*SSTR)   // 20480

template<int MODE>
__global__ void __launch_bounds__(256)
gemm_proj(const __nv_bfloat16* __restrict__ Ah, const __nv_bfloat16* __restrict__ Al,
          const __nv_bfloat16* __restrict__ Bh, const __nv_bfloat16* __restrict__ Bl,
          float* __restrict__ C, __nv_bfloat16* __restrict__ H, __nv_bfloat16* __restrict__ L)
{
    extern __shared__ char smem[];
    uint32_t sb = smem_u32(smem);
    const int tid = threadIdx.x, lane = tid & 31, warp = tid >> 5;
    const int rowBase = blockIdx.y * 128, colBase = blockIdx.x * 128;
    const int wrow = (warp >> 2) * 64, wcol = (warp & 3) * 32;

    float cfr[16][4];
#pragma unroll
    for (int i = 0; i < 16; i++)
#pragma unroll
        for (int j = 0; j < 4; j++) cfr[i][j] = 0.f;

#define PROJ_PTRS(c, ap, bp) {                                        \
        int term = (c) >> 5, k0 = ((c) & 31) << 5;                    \
        const __nv_bfloat16* As = (term < 2) ? Ah : Al;               \
        const __nv_bfloat16* Bs = (term == 1) ? Bl : Bh;              \
        ap = As + (size_t)rowBase * EMB + k0;                         \
        bp = Bs + (size_t)colBase * EMB + k0; }

    for (int c = 0; c < 3; c++) {
        const __nv_bfloat16 *ap, *bp; PROJ_PTRS(c, ap, bp);
        uint32_t st = sb + c * STAGE_PROJ;
        fill_rows(st, ap, EMB, 128, tid);
        fill_rows(st + A_BYTES, bp, EMB, 128, tid);
        CP_COMMIT();
    }
    for (int c = 0; c < PROJ_CHUNKS; c++) {
        CP_WAIT2();
        __syncthreads();
        if (c + 3 < PROJ_CHUNKS) {
            const __nv_bfloat16 *ap, *bp; PROJ_PTRS(c + 3, ap, bp);
            uint32_t st = sb + ((c + 3) & 3) * STAGE_PROJ;
            fill_rows(st, ap, EMB, 128, tid);
            fill_rows(st + A_BYTES, bp, EMB, 128, tid);
            CP_COMMIT();
        }
        uint32_t st = sb + (c & 3) * STAGE_PROJ;
        compute_stage<4, 2>(st, st + A_BYTES, wrow, wcol, lane, cfr);
    }

#pragma unroll
    for (int mt = 0; mt < 4; mt++)
#pragma unroll
        for (int np = 0; np < 2; np++)
#pragma unroll
            for (int t8 = 0; t8 < 2; t8++) {
                int nt = np * 2 + t8;
                int row = rowBase + wrow + mt * 16 + (lane >> 2);
                int col = colBase + wcol + nt * 8 + 2 * (lane & 3);
                float* cc = cfr[(mt * 2 + np) * 2 + t8];
#pragma unroll
                for (int half = 0; half < 2; half++) {
                    int r = row + half * 8;
                    float v0 = cc[half * 2], v1 = cc[half * 2 + 1];
                    if (MODE == 0) {
                        *(float2*)(C + (size_t)r * EMB + col) = make_float2(v0, v1);
                    } else {
                        __nv_bfloat16 h0, h1, l0, l1;
                        split2(v0, h0, l0); split2(v1, h1, l1);
                        *(uint32_t*)(H + (size_t)r * EMB + col) = pack2(h0, h1);
                        *(uint32_t*)(L + (size_t)r * EMB + col) = pack2(l0, l1);
                    }
                }
            }
}

// ---------------- QK^T GEMM: E[z][ti][tj] = 8 * TQ . K^T ---------------------
#define QK_CHUNKS 6
__global__ void __launch_bounds__(256)
gemm_qk()
{
    extern __shared__ char smem[];
    uint32_t sb = smem_u32(smem);
    const int tid = threadIdx.x, lane = tid & 31, warp = tid >> 5;
    const int rowBase = blockIdx.y * 128, colBase = blockIdx.x * 128;
    const int z = blockIdx.z, b = z >> 4, h = z & 15;
    const int wrow = (warp >> 2) * 64, wcol = (warp & 3) * 32;
    const size_t aoff = (size_t)(b * SEQ + rowBase) * EMB + h * DHEAD;
    const size_t boff = (size_t)(b * SEQ + colBase) * EMB + h * DHEAD;

    float cfr[16][4];
#pragma unroll
    for (int i = 0; i < 16; i++)
#pragma unroll
        for (int j = 0; j < 4; j++) cfr[i][j] = 0.f;

#define QK_PTRS(c, ap, bp) {                                          \
        int term = (c) >> 1, k0 = ((c) & 1) << 5;                     \
        const __nv_bfloat16* As = (term < 2) ? g_TQh : g_TQl;         \
        const __nv_bfloat16* Bs = (term == 1) ? g_Kl : g_Kh;          \
        ap = As + aoff + k0;  bp = Bs + boff + k0; }

    for (int c = 0; c < 3; c++) {
        const __nv_bfloat16 *ap, *bp; QK_PTRS(c, ap, bp);
        uint32_t st = sb + c * STAGE_PROJ;
        fill_rows(st, ap, EMB, 128, tid);
        fill_rows(st + A_BYTES, bp, EMB, 128, tid);
        CP_COMMIT();
    }
    for (int c = 0; c < QK_CHUNKS; c++) {
        CP_WAIT2();
        __syncthreads();
        if (c + 3 < QK_CHUNKS) {
            const __nv_bfloat16 *ap, *bp; QK_PTRS(c + 3, ap, bp);
            uint32_t st = sb + ((c + 3) & 3) * STAGE_PROJ;
            fill_rows(st, ap, EMB, 128, tid);
            fill_rows(st + A_BYTES, bp, EMB, 128, tid);
            CP_COMMIT();
        }
        uint32_t st = sb + (c & 3) * STAGE_PROJ;
        compute_stage<4, 2>(st, st + A_BYTES, wrow, wcol, lane, cfr);
    }

    float* E = g_E + (size_t)z * SEQ * SEQ;
#pragma unroll
    for (int mt = 0; mt < 4; mt++)
#pragma unroll
        for (int np = 0; np < 2; np++)
#pragma unroll
            for (int t8 = 0; t8 < 2; t8++) {
                int nt = np * 2 + t8;
                int row = rowBase + wrow + mt * 16 + (lane >> 2);
                int col = colBase + wcol + nt * 8 + 2 * (lane & 3);
                float* cc = cfr[(mt * 2 + np) * 2 + t8];
#pragma unroll
                for (int half = 0; half < 2; half++) {
                    int r = row + half * 8;
                    *(float2*)(E + (size_t)r * SEQ + col) =
                        make_float2(cc[half * 2] * 8.0f, cc[half * 2 + 1] * 8.0f);
                }
            }
}

// ---------------- row softmax: E -> Ph/Pl (bf16 split) -----------------------
__global__ void __launch_bounds__(256)
softmax_kernel()
{
    const int lane = threadIdx.x & 31, warp = threadIdx.x >> 5;
    const size_t row = (size_t)blockIdx.x * 8 + warp;
    const float* e = g_E + row * SEQ;
    float4 v[16];
    float m = -INFINITY;
#pragma unroll
    for (int i = 0; i < 16; i++) {
        v[i] = ((const float4*)e)[i * 32 + lane];
        m = fmaxf(m, fmaxf(fmaxf(v[i].x, v[i].y), fmaxf(v[i].z, v[i].w)));
    }
#pragma unroll
    for (int o = 16; o > 0; o >>= 1) m = fmaxf(m, __shfl_xor_sync(0xffffffffu, m, o));
    float s = 0.f;
#pragma unroll
    for (int i = 0; i < 16; i++) {
        v[i].x = __expf(v[i].x - m); v[i].y = __expf(v[i].y - m);
        v[i].z = __expf(v[i].z - m); v[i].w = __expf(v[i].w - m);
        s += v[i].x + v[i].y + v[i].z + v[i].w;
    }
#pragma unroll
    for (int o = 16; o > 0; o >>= 1) s += __shfl_xor_sync(0xffffffffu, s, o);
    float inv = 1.0f / s;
    __nv_bfloat16* Ph = g_Ph + row * SEQ;
    __nv_bfloat16* Pl = g_Pl + row * SEQ;
#pragma unroll
    for (int i = 0; i < 16; i++) {
        float p0 = v[i].x * inv, p1 = v[i].y * inv, p2 = v[i].z * inv, p3 = v[i].w * inv;
        __nv_bfloat16 h0, h1, h2, h3, l0, l1, l2, l3;
        split2(p0, h0, l0); split2(p1, h1, l1);
        split2(p2, h2, l2); split2(p3, h3, l3);
        ((uint2*)Ph)[i * 32 + lane] = make_uint2(pack2(h0, h1), pack2(h2, h3));
        ((uint2*)Pl)[i * 32 + lane] = make_uint2(pack2(l0, l1), pack2(l2, l3));
    }
}

// ---------------- V transpose: g_V fp32 -> Vt[z][d][t] bf16 split ------------
__global__ void transpose_v()
{
    __shared__ float tile[32][33];
    const int z = blockIdx.z, b = z >> 4, h = z & 15;
    const int t0 = blockIdx.x * 32, d0 = blockIdx.y * 32;
    const int tx = threadIdx.x, ty = threadIdx.y;   // (32, 8)
#pragma unroll
    for (int j = 0; j < 4; j++) {
        int t = t0 + ty + j * 8;
        tile[ty + j * 8][tx] = g_V[(size_t)(b * SEQ + t) * EMB + h * DHEAD + d0 + tx];
    }
    __syncthreads();
#pragma unroll
    for (int j = 0; j < 4; j++) {
        int d = d0 + ty + j * 8;
        float val = tile[tx][ty + j * 8];
        __nv_bfloat16 hh, ll;
        split2(val, hh, ll);
        size_t idx = ((size_t)z * DHEAD + d) * SEQ + t0 + tx;
        g_Vth[idx] = hh; g_Vtl[idx] = ll;
    }
}

// ---------------- PV GEMM: O[z][ti][d] = P . V -------------------------------
#define PV_CHUNKS 192
#define STAGE_PV (A_BYTES + 64*SSTR)   // 15360
__global__ void __launch_bounds__(256)
gemm_pv()
{
    extern __shared__ char smem[];
    uint32_t sb = smem_u32(smem);
    const int tid = threadIdx.x, lane = tid & 31, warp = tid >> 5;
    const int rowBase = blockIdx.x * 128;
    const int z = blockIdx.y, b = z >> 4, h = z & 15;
    const int wrow = (warp >> 1) * 32, wcol = (warp & 1) * 32;
    const size_t aoff = (size_t)z * SEQ * SEQ + (size_t)rowBase * SEQ;
    const size_t boff = (size_t)z * DHEAD * SEQ;

    float cfr[8][4];
#pragma unroll
    for (int i = 0; i < 8; i++)
#pragma unroll
        for (int j = 0; j < 4; j++) cfr[i][j] = 0.f;

#define PV_PTRS(c, ap, bp) {                                          \
        int term = (c) >> 6, k0 = ((c) & 63) << 5;                    \
        const __nv_bfloat16* As = (term < 2) ? g_Ph : g_Pl;           \
        const __nv_bfloat16* Bs = (term == 1) ? g_Vtl : g_Vth;        \
        ap = As + aoff + k0;  bp = Bs + boff + k0; }

    for (int c = 0; c < 3; c++) {
        const __nv_bfloat16 *ap, *bp; PV_PTRS(c, ap, bp);
        uint32_t st = sb + c * STAGE_PV;
        fill_rows(st, ap, SEQ, 128, tid);
        fill_rows(st + A_BYTES, bp, SEQ, 64, tid);
        CP_COMMIT();
    }
    for (int c = 0; c < PV_CHUNKS; c++) {
        CP_WAIT2();
        __syncthreads();
        if (c + 3 < PV_CHUNKS) {
            const __nv_bfloat16 *ap, *bp; PV_PTRS(c + 3, ap, bp);
            uint32_t st = sb + ((c + 3) & 3) * STAGE_PV;
            fill_rows(st, ap, SEQ, 128, tid);
            fill_rows(st + A_BYTES, bp, SEQ, 64, tid);
            CP_COMMIT();
        }
        uint32_t st = sb + (c & 3) * STAGE_PV;
        compute_stage<2, 2>(st, st + A_BYTES, wrow, wcol, lane, cfr);
    }

#pragma unroll
    for (int mt = 0; mt < 2; mt++)
#pragma unroll
        for (int np = 0; np < 2; np++)
#pragma unroll
            for (int t8 = 0; t8 < 2; t8++) {
                int nt = np * 2 + t8;
                int row = rowBase + wrow + mt * 16 + (lane >> 2);
                int col = wcol + nt * 8 + 2 * (lane & 3);   // d in [0,64)
                float* cc = cfr[(mt * 2 + np) * 2 + t8];
#pragma unroll
                for (int half = 0; half < 2; half++) {
                    int r = row + half * 8;
                    size_t idx = (size_t)(b * SEQ + r) * EMB + h * DHEAD + col;
                    __nv_bfloat16 h0, h1, l0, l1;
                    split2(cc[half * 2], h0, l0); split2(cc[half * 2 + 1], h1, l1);
                    *(uint32_t*)(g_Oh + idx) = pack2(h0, h1);
                    *(uint32_t*)(g_Ol + idx) = pack2(l0, l1);
                }
            }
}

// ---------------- launch ------------------------------------------------------
extern "C" void kernel_launch(void* const* d_in, const int* in_sizes, int n_in,
                              void* d_out, int out_size)
{
    const float* x     = (const float*)d_in[0];
    const float* tx    = (const float*)d_in[1];
    const float* Wqkv  = (const float*)d_in[2];
    const float* Wtqkv = (const float*)d_in[3];
    const float* Wout  = (const float*)d_in[4];
    float* out = (float*)d_out;

    __nv_bfloat16 *pxh, *pxl, *ptxh, *ptxl, *pKh, *pKl, *pTQh, *pTQl, *pOh, *pOl;
    __nv_bfloat16 *pWkh, *pWkl, *pWvh, *pWvl, *pWtqh, *pWtql, *pWoh, *pWol;
    float *pV;
    cudaGetSymbolAddress((void**)&pxh,  g_xh);  cudaGetSymbolAddress((void**)&pxl,  g_xl);
    cudaGetSymbolAddress((void**)&ptxh, g_txh); cudaGetSymbolAddress((void**)&ptxl, g_txl);
    cudaGetSymbolAddress((void**)&pKh,  g_Kh);  cudaGetSymbolAddress((void**)&pKl,  g_Kl);
    cudaGetSymbolAddress((void**)&pTQh, g_TQh); cudaGetSymbolAddress((void**)&pTQl, g_TQl);
    cudaGetSymbolAddress((void**)&pOh,  g_Oh);  cudaGetSymbolAddress((void**)&pOl,  g_Ol);
    cudaGetSymbolAddress((void**)&pV,   g_V);
    cudaGetSymbolAddress((void**)&pWkh, g_Wkh); cudaGetSymbolAddress((void**)&pWkl, g_Wkl);
    cudaGetSymbolAddress((void**)&pWvh, g_Wvh); cudaGetSymbolAddress((void**)&pWvl, g_Wvl);
    cudaGetSymbolAddress((void**)&pWtqh,g_Wtqh);cudaGetSymbolAddress((void**)&pWtql,g_Wtql);
    cudaGetSymbolAddress((void**)&pWoh, g_Wouth);cudaGetSymbolAddress((void**)&pWol, g_Woutl);

    cudaFuncSetAttribute(gemm_proj<0>, cudaFuncAttributeMaxDynamicSharedMemorySize, 4 * STAGE_PROJ);
    cudaFuncSetAttribute(gemm_proj<1>, cudaFuncAttributeMaxDynamicSharedMemorySize, 4 * STAGE_PROJ);
    cudaFuncSetAttribute(gemm_qk,      cudaFuncAttributeMaxDynamicSharedMemorySize, 4 * STAGE_PROJ);
    cudaFuncSetAttribute(gemm_pv,      cudaFuncAttributeMaxDynamicSharedMemorySize, 4 * STAGE_PV);

    int nBig = MROWS * EMB, nW = EMB * EMB;
    split_convert<<<nBig/4/256, 256>>>(x,  pxh,  pxl,  nBig);
    split_convert<<<nBig/4/256, 256>>>(tx, ptxh, ptxl, nBig);
    split_convert<<<nW/4/256,   256>>>(Wout, pWoh, pWol, nW);
    permute_split_w<<<dim3(EMB/256, EMB), 256>>>(Wqkv, Wtqkv);

    dim3 pg(EMB/128, MROWS/128);   // (8, 32)
    gemm_proj<1><<<pg, 256, 4*STAGE_PROJ>>>(pxh,  pxl,  pWkh,  pWkl,  nullptr, pKh,  pKl);
    gemm_proj<0><<<pg, 256, 4*STAGE_PROJ>>>(pxh,  pxl,  pWvh,  pWvl,  pV,      nullptr, nullptr);
    gemm_proj<1><<<pg, 256, 4*STAGE_PROJ>>>(ptxh, ptxl, pWtqh, pWtql, nullptr, pTQh, pTQl);

    transpose_v<<<dim3(SEQ/32, DHEAD/32, NSLICE), dim3(32, 8)>>>();

    gemm_qk<<<dim3(SEQ/128, SEQ/128, NSLICE), 256, 4*STAGE_PROJ>>>();
    softmax_kernel<<<(NSLICE*SEQ)/8, 256>>>();
    gemm_pv<<<dim3(SEQ/128, NSLICE), 256, 4*STAGE_PV>>>();

    gemm_proj<0><<<pg, 256, 4*STAGE_PROJ>>>(pOh, pOl, pWoh, pWol, out, nullptr, nullptr);
}

// round 4
// speedup vs baseline: 4.3440x; 1.2603x over previous
#include <cuda_runtime.h>
#include <cuda_bf16.h>
#include <math.h>
#include <stdint.h>

#define BATCH 2
#define SEQ   2048
#define EMB   1024
#define HEADS 16
#define DHEAD 64
#define MROWS (BATCH*SEQ)         // 4096
#define NSLICE (BATCH*HEADS)      // 32

// ---------------- scratch (static device globals; no allocation) -------------
__device__ __nv_bfloat16 g_xh [MROWS*EMB], g_xl [MROWS*EMB];
__device__ __nv_bfloat16 g_txh[MROWS*EMB], g_txl[MROWS*EMB];
__device__ __nv_bfloat16 g_Kh [MROWS*EMB], g_Kl [MROWS*EMB];
__device__ __nv_bfloat16 g_TQh[MROWS*EMB], g_TQl[MROWS*EMB];
__device__ float         g_V  [MROWS*EMB];
__device__ __nv_bfloat16 g_Vth[NSLICE*DHEAD*SEQ], g_Vtl[NSLICE*DHEAD*SEQ];
__device__ __nv_bfloat16 g_Oh [MROWS*EMB], g_Ol [MROWS*EMB];
__device__ __nv_bfloat16 g_Wkh [EMB*EMB], g_Wkl [EMB*EMB];
__device__ __nv_bfloat16 g_Wvh [EMB*EMB], g_Wvl [EMB*EMB];
__device__ __nv_bfloat16 g_Wtqh[EMB*EMB], g_Wtql[EMB*EMB];
__device__ __nv_bfloat16 g_Wouth[EMB*EMB], g_Woutl[EMB*EMB];

// ---------------- small helpers ----------------------------------------------
__device__ __forceinline__ uint32_t smem_u32(const void* p) {
    uint32_t a;
    asm("{ .reg .u64 t; cvta.to.shared.u64 t, %1; cvt.u32.u64 %0, t; }" : "=r"(a) : "l"(p));
    return a;
}
#define CP_ASYNC16(dst, src) \
    asm volatile("cp.async.cg.shared.global [%0], [%1], 16;" :: "r"(dst), "l"(src) : "memory")
#define CP_COMMIT() asm volatile("cp.async.commit_group;" ::: "memory")
#define CP_WAIT2()  asm volatile("cp.async.wait_group 2;" ::: "memory")
#define CP_WAIT1()  asm volatile("cp.async.wait_group 1;" ::: "memory")
#define CP_WAIT0()  asm volatile("cp.async.wait_group 0;" ::: "memory")

__device__ __forceinline__ void ldsm_x4(uint32_t r[4], uint32_t addr) {
    asm volatile("ldmatrix.sync.aligned.m8n8.x4.shared.b16 {%0,%1,%2,%3}, [%4];"
                 : "=r"(r[0]), "=r"(r[1]), "=r"(r[2]), "=r"(r[3]) : "r"(addr));
}
__device__ __forceinline__ void mma16816(float c[4], const uint32_t a[4],
                                         uint32_t b0, uint32_t b1) {
    asm volatile("mma.sync.aligned.m16n8k16.row.col.f32.bf16.bf16.f32 "
                 "{%0,%1,%2,%3},{%4,%5,%6,%7},{%8,%9},{%0,%1,%2,%3};"
                 : "+f"(c[0]), "+f"(c[1]), "+f"(c[2]), "+f"(c[3])
                 : "r"(a[0]), "r"(a[1]), "r"(a[2]), "r"(a[3]), "r"(b0), "r"(b1));
}
__device__ __forceinline__ uint32_t pack2(__nv_bfloat16 a, __nv_bfloat16 b) {
    return (uint32_t)__bfloat16_as_ushort(a) | ((uint32_t)__bfloat16_as_ushort(b) << 16);
}
__device__ __forceinline__ void split2(float x, __nv_bfloat16& h, __nv_bfloat16& l) {
    h = __float2bfloat16(x);
    l = __float2bfloat16(x - __bfloat162float(h));
}

// smem tile geometry
#define SSTR 80              // 32-half rows (projection GEMMs)
#define A_BYTES (128*SSTR)   // 10240
#define SSTR64 144           // 64-half rows (flash kernel), conflict-free
#define TILE_B (64*SSTR64)   // 9216

__device__ __forceinline__ void fill_rows(uint32_t dst, const __nv_bfloat16* src,
                                          int ld, int rows, int tid) {
    for (int j = tid; j < rows * 4; j += 256) {
        int r = j >> 2, cc = j & 3;
        CP_ASYNC16(dst + r * SSTR + cc * 16, src + (size_t)r * ld + cc * 8);
    }
}

// warp-level compute over one stage: MT m16-tiles, NP pairs of n8-tiles, BK=32
template<int MT, int NP>
__device__ __forceinline__ void compute_stage(uint32_t abase, uint32_t bbase,
                                              int wrow, int wcol, int lane,
                                              float (*cfr)[4]) {
    const int arow  = wrow + (lane & 15);
    const int acolh = (lane >> 4) * 8;
    const int brow  = wcol + (lane & 7) + ((lane >> 4) << 3);
    const int bcolh = ((lane >> 3) & 1) * 8;
#pragma unroll
    for (int ks = 0; ks < 2; ks++) {
        uint32_t a[MT][4], b[NP][4];
#pragma unroll
        for (int mt = 0; mt < MT; mt++)
            ldsm_x4(a[mt], abase + (uint32_t)(arow + mt * 16) * SSTR + (acolh + ks * 16) * 2);
#pragma unroll
        for (int np = 0; np < NP; np++)
            ldsm_x4(b[np], bbase + (uint32_t)(brow + np * 16) * SSTR + (bcolh + ks * 16) * 2);
#pragma unroll
        for (int mt = 0; mt < MT; mt++)
#pragma unroll
            for (int np = 0; np < NP; np++) {
                mma16816(cfr[(mt * NP + np) * 2 + 0], a[mt], b[np][0], b[np][1]);
                mma16816(cfr[(mt * NP + np) * 2 + 1], a[mt], b[np][2], b[np][3]);
            }
    }
}

// ---------------- conversion kernels -----------------------------------------
__global__ void split_convert(const float* __restrict__ X,
                              __nv_bfloat16* __restrict__ H,
                              __nv_bfloat16* __restrict__ L, int n)
{
    int i = blockIdx.x * blockDim.x + threadIdx.x;
    if (i >= n / 4) return;
    float4 v = ((const float4*)X)[i];
    __nv_bfloat16 h0, h1, h2, h3, l0, l1, l2, l3;
    split2(v.x, h0, l0); split2(v.y, h1, l1);
    split2(v.z, h2, l2); split2(v.w, h3, l3);
    ((uint2*)H)[i] = make_uint2(pack2(h0, h1), pack2(h2, h3));
    ((uint2*)L)[i] = make_uint2(pack2(l0, l1), pack2(l2, l3));
}

__global__ void permute_split_w(const float* __restrict__ Wqkv,
                                const float* __restrict__ Wtqkv)
{
    int k = blockIdx.x * 256 + threadIdx.x;
    int n = blockIdx.y;
    int h = n >> 6, d = n & 63;
    size_t dst = (size_t)n * EMB + k;
    float vk  = Wqkv [(size_t)(d * 48 + 16 + h) * EMB + k];
    float vv  = Wqkv [(size_t)(d * 48 + 32 + h) * EMB + k];
    float vtq = Wtqkv[(size_t)(d * 48 +  0 + h) * EMB + k];
    __nv_bfloat16 hh, ll;
    split2(vk,  hh, ll); g_Wkh [dst] = hh; g_Wkl [dst] = ll;
    split2(vv,  hh, ll); g_Wvh [dst] = hh; g_Wvl [dst] = ll;
    split2(vtq, hh, ll); g_Wtqh[dst] = hh; g_Wtql[dst] = ll;
}

// ---------------- projection / output GEMM -----------------------------------
#define PROJ_CHUNKS 96
#define STAGE_PROJ (A_BYTES + 128*SSTR)   // 20480

template<int MODE>
__global__ void __launch_bounds__(256)
gemm_proj(const __nv_bfloat16* __restrict__ Ah, const __nv_bfloat16* __restrict__ Al,
          const __nv_bfloat16* __restrict__ Bh, const __nv_bfloat16* __restrict__ Bl,
          float* __restrict__ C, __nv_bfloat16* __restrict__ H, __nv_bfloat16* __restrict__ L)
{
    extern __shared__ char smem[];
    uint32_t sb = smem_u32(smem);
    const int tid = threadIdx.x, lane = tid & 31, warp = tid >> 5;
    const int rowBase = blockIdx.y * 128, colBase = blockIdx.x * 128;
    const int wrow = (warp >> 2) * 64, wcol = (warp & 3) * 32;

    float cfr[16][4];
#pragma unroll
    for (int i = 0; i < 16; i++)
#pragma unroll
        for (int j = 0; j < 4; j++) cfr[i][j] = 0.f;

#define PROJ_PTRS(c, ap, bp) {                                        \
        int term = (c) >> 5, k0 = ((c) & 31) << 5;                    \
        const __nv_bfloat16* As = (term < 2) ? Ah : Al;               \
        const __nv_bfloat16* Bs = (term == 1) ? Bl : Bh;              \
        ap = As + (size_t)rowBase * EMB + k0;                         \
        bp = Bs + (size_t)colBase * EMB + k0; }

    for (int c = 0; c < 3; c++) {
        const __nv_bfloat16 *ap, *bp; PROJ_PTRS(c, ap, bp);
        uint32_t st = sb + c * STAGE_PROJ;
        fill_rows(st, ap, EMB, 128, tid);
        fill_rows(st + A_BYTES, bp, EMB, 128, tid);
        CP_COMMIT();
    }
    for (int c = 0; c < PROJ_CHUNKS; c++) {
        CP_WAIT2();
        __syncthreads();
        if (c + 3 < PROJ_CHUNKS) {
            const __nv_bfloat16 *ap, *bp; PROJ_PTRS(c + 3, ap, bp);
            uint32_t st = sb + ((c + 3) & 3) * STAGE_PROJ;
            fill_rows(st, ap, EMB, 128, tid);
            fill_rows(st + A_BYTES, bp, EMB, 128, tid);
            CP_COMMIT();
        }
        uint32_t st = sb + (c & 3) * STAGE_PROJ;
        compute_stage<4, 2>(st, st + A_BYTES, wrow, wcol, lane, cfr);
    }

#pragma unroll
    for (int mt = 0; mt < 4; mt++)
#pragma unroll
        for (int np = 0; np < 2; np++)
#pragma unroll
            for (int t8 = 0; t8 < 2; t8++) {
                int nt = np * 2 + t8;
                int row = rowBase + wrow + mt * 16 + (lane >> 2);
                int col = colBase + wcol + nt * 8 + 2 * (lane & 3);
                float* cc = cfr[(mt * 2 + np) * 2 + t8];
#pragma unroll
                for (int half = 0; half < 2; half++) {
                    int r = row + half * 8;
                    float v0 = cc[half * 2], v1 = cc[half * 2 + 1];
                    if (MODE == 0) {
                        *(float2*)(C + (size_t)r * EMB + col) = make_float2(v0, v1);
                    } else {
                        __nv_bfloat16 h0, h1, l0, l1;
                        split2(v0, h0, l0); split2(v1, h1, l1);
                        *(uint32_t*)(H + (size_t)r * EMB + col) = pack2(h0, h1);
                        *(uint32_t*)(L + (size_t)r * EMB + col) = pack2(l0, l1);
                    }
                }
            }
}

// ---------------- V transpose: g_V fp32 -> Vt[z][d][t] bf16 split ------------
__global__ void transpose_v()
{
    __shared__ float tile[32][33];
    const int z = blockIdx.z, b = z >> 4, h = z & 15;
    const int t0 = blockIdx.x * 32, d0 = blockIdx.y * 32;
    const int tx = threadIdx.x, ty = threadIdx.y;   // (32, 8)
#pragma unroll
    for (int j = 0; j < 4; j++) {
        int t = t0 + ty + j * 8;
        tile[ty + j * 8][tx] = g_V[(size_t)(b * SEQ + t) * EMB + h * DHEAD + d0 + tx];
    }
    __syncthreads();
#pragma unroll
    for (int j = 0; j < 4; j++) {
        int d = d0 + ty + j * 8;
        float val = tile[tx][ty + j * 8];
        __nv_bfloat16 hh, ll;
        split2(val, hh, ll);
        size_t idx = ((size_t)z * DHEAD + d) * SEQ + t0 + tx;
        g_Vth[idx] = hh; g_Vtl[idx] = ll;
    }
}

// ---------------- fused flash attention (HMMA, 3-term split) -----------------
// stage layout: [Kh | Kl | Vth | Vtl], each 64 rows x 144B
#define FSTAGE (4*TILE_B)    // 36864
#define FSMEM  (2*FSTAGE)    // 73728

__device__ __forceinline__ void fill_kv(uint32_t st, int t, int b, int h, int z, int tid)
{
    const size_t koff = (size_t)(b * SEQ + t * 64) * EMB + h * DHEAD;
    const size_t voff = (size_t)z * DHEAD * SEQ + t * 64;
    for (int j = tid; j < 64 * 8; j += 256) {
        int r = j >> 3, c = j & 7;
        uint32_t d = (uint32_t)r * SSTR64 + c * 16;
        size_t ko = koff + (size_t)r * EMB + c * 8;
        size_t vo = voff + (size_t)r * SEQ + c * 8;
        CP_ASYNC16(st + d,              g_Kh  + ko);
        CP_ASYNC16(st + TILE_B + d,     g_Kl  + ko);
        CP_ASYNC16(st + 2 * TILE_B + d, g_Vth + vo);
        CP_ASYNC16(st + 3 * TILE_B + d, g_Vtl + vo);
    }
}

__device__ __forceinline__ void qk_pass(uint32_t bbase, const uint32_t A[4][4],
                                        float (*s)[4], int lane)
{
    const int brow  = (lane & 7) + ((lane >> 4) << 3);
    const int bcolh = ((lane >> 3) & 1) * 8;
#pragma unroll
    for (int ks = 0; ks < 4; ks++) {
#pragma unroll
        for (int pr = 0; pr < 4; pr++) {
            uint32_t bf[4];
            ldsm_x4(bf, bbase + (uint32_t)(brow + pr * 16) * SSTR64 + (bcolh + ks * 16) * 2);
            mma16816(s[pr * 2 + 0], A[ks], bf[0], bf[1]);
            mma16816(s[pr * 2 + 1], A[ks], bf[2], bf[3]);
        }
    }
}

template<int LO>
__device__ __forceinline__ void pv_pass(uint32_t bbase, const float (*s)[4],
                                        float (*o)[4], int lane)
{
    const int brow  = (lane & 7) + ((lane >> 4) << 3);
    const int bcolh = ((lane >> 3) & 1) * 8;
#pragma unroll
    for (int ks = 0; ks < 4; ks++) {
        const float* c0 = s[2 * ks];
        const float* c1 = s[2 * ks + 1];
        uint32_t A[4];
        if (!LO) {
            A[0] = pack2(__float2bfloat16(c0[0]), __float2bfloat16(c0[1]));
            A[1] = pack2(__float2bfloat16(c0[2]), __float2bfloat16(c0[3]));
            A[2] = pack2(__float2bfloat16(c1[0]), __float2bfloat16(c1[1]));
            A[3] = pack2(__float2bfloat16(c1[2]), __float2bfloat16(c1[3]));
        } else {
            __nv_bfloat16 h, l;
#define RES(v) (split2((v), h, l), l)
            A[0] = pack2(RES(c0[0]), RES(c0[1]));
            A[1] = pack2(RES(c0[2]), RES(c0[3]));
            A[2] = pack2(RES(c1[0]), RES(c1[1]));
            A[3] = pack2(RES(c1[2]), RES(c1[3]));
#undef RES
        }
#pragma unroll
        for (int pr = 0; pr < 4; pr++) {
            uint32_t bf[4];
            ldsm_x4(bf, bbase + (uint32_t)(brow + pr * 16) * SSTR64 + (bcolh + ks * 16) * 2);
            mma16816(o[pr * 2 + 0], A, bf[0], bf[1]);
            mma16816(o[pr * 2 + 1], A, bf[2], bf[3]);
        }
    }
}

__global__ void __launch_bounds__(256)
flash_attn()
{
    extern __shared__ char smem[];
    uint32_t sb = smem_u32(smem);
    const int tid = threadIdx.x, lane = tid & 31, warp = tid >> 5;
    const int rowBase = blockIdx.x * 128;
    const int z = blockIdx.y, b = z >> 4, h = z & 15;
    const int wrow = warp * 16;

    // ---- stage TQ (128 rows x 64 d, hi+lo) into stage0 area, hoist A-frags --
    {
        const size_t toff = (size_t)(b * SEQ + rowBase) * EMB + h * DHEAD;
        for (int j = tid; j < 128 * 8; j += 256) {
            int r = j >> 3, c = j & 7;
            uint32_t d = (uint32_t)r * SSTR64 + c * 16;
            size_t go = toff + (size_t)r * EMB + c * 8;
            CP_ASYNC16(sb + d,         g_TQh + go);
            CP_ASYNC16(sb + 18432 + d, g_TQl + go);
        }
        CP_COMMIT(); CP_WAIT0();
    }
    __syncthreads();

    uint32_t aqh[4][4], aql[4][4];
    {
        const int arow  = wrow + (lane & 15);
        const int acolh = (lane >> 4) * 8;
#pragma unroll
        for (int ks = 0; ks < 4; ks++) {
            ldsm_x4(aqh[ks], sb + (uint32_t)arow * SSTR64 + (acolh + ks * 16) * 2);
            ldsm_x4(aql[ks], sb + 18432 + (uint32_t)arow * SSTR64 + (acolh + ks * 16) * 2);
        }
    }
    __syncthreads();   // stage0 free for K/V now

    float o[8][4];
#pragma unroll
    for (int i = 0; i < 8; i++)
#pragma unroll
        for (int j = 0; j < 4; j++) o[i][j] = 0.f;
    float m0 = -INFINITY, m1 = -INFINITY, l0 = 0.f, l1 = 0.f;

    fill_kv(sb, 0, b, h, z, tid);
    CP_COMMIT();

    for (int t = 0; t < SEQ / 64; t++) {
        if (t + 1 < SEQ / 64) {
            fill_kv(sb + ((t + 1) & 1) * FSTAGE, t + 1, b, h, z, tid);
            CP_COMMIT();
            CP_WAIT1();
        } else {
            CP_WAIT0();
        }
        __syncthreads();
        uint32_t st = sb + (t & 1) * FSTAGE;

        // ---- S = 8 * TQ . K^T  (3-term) ----
        float s[8][4];
#pragma unroll
        for (int i = 0; i < 8; i++)
#pragma unroll
            for (int j = 0; j < 4; j++) s[i][j] = 0.f;
        qk_pass(st,          aqh, s, lane);   // TQh . Kh
        qk_pass(st + TILE_B, aqh, s, lane);   // TQh . Kl
        qk_pass(st,          aql, s, lane);   // TQl . Kh

        // ---- online softmax ----
        float rm0 = -INFINITY, rm1 = -INFINITY;
#pragma unroll
        for (int i = 0; i < 8; i++) {
            s[i][0] *= 8.f; s[i][1] *= 8.f; s[i][2] *= 8.f; s[i][3] *= 8.f;
            rm0 = fmaxf(rm0, fmaxf(s[i][0], s[i][1]));
            rm1 = fmaxf(rm1, fmaxf(s[i][2], s[i][3]));
        }
        rm0 = fmaxf(rm0, __shfl_xor_sync(0xffffffffu, rm0, 1));
        rm0 = fmaxf(rm0, __shfl_xor_sync(0xffffffffu, rm0, 2));
        rm1 = fmaxf(rm1, __shfl_xor_sync(0xffffffffu, rm1, 1));
        rm1 = fmaxf(rm1, __shfl_xor_sync(0xffffffffu, rm1, 2));
        float mn0 = fmaxf(m0, rm0), mn1 = fmaxf(m1, rm1);
        float c0 = __expf(m0 - mn0), c1 = __expf(m1 - mn1);
        l0 *= c0; l1 *= c1;
#pragma unroll
        for (int i = 0; i < 8; i++) {
            o[i][0] *= c0; o[i][1] *= c0; o[i][2] *= c1; o[i][3] *= c1;
            float p0 = __expf(s[i][0] - mn0), p1 = __expf(s[i][1] - mn0);
            float p2 = __expf(s[i][2] - mn1), p3 = __expf(s[i][3] - mn1);
            s[i][0] = p0; s[i][1] = p1; s[i][2] = p2; s[i][3] = p3;
            l0 += p0 + p1; l1 += p2 + p3;
        }
        m0 = mn0; m1 = mn1;

        // ---- O += P . V  (3-term) ----
        pv_pass<0>(st + 2 * TILE_B, s, o, lane);  // Ph . Vh
        pv_pass<1>(st + 2 * TILE_B, s, o, lane);  // Pl . Vh
        pv_pass<0>(st + 3 * TILE_B, s, o, lane);  // Ph . Vl
        __syncthreads();
    }

    // ---- finalize: divide by row sums, write split bf16 ----
    l0 += __shfl_xor_sync(0xffffffffu, l0, 1);
    l0 += __shfl_xor_sync(0xffffffffu, l0, 2);
    l1 += __shfl_xor_sync(0xffffffffu, l1, 1);
    l1 += __shfl_xor_sync(0xffffffffu, l1, 2);
    float inv0 = 1.f / l0, inv1 = 1.f / l1;

    const int row0 = rowBase + wrow + (lane >> 2);
#pragma unroll
    for (int j = 0; j < 8; j++) {
        int col = h * DHEAD + j * 8 + 2 * (lane & 3);
        size_t i0 = (size_t)(b * SEQ + row0) * EMB + col;
        size_t i1 = (size_t)(b * SEQ + row0 + 8) * EMB + col;
        __nv_bfloat16 h0, h1, lo0, lo1;
        split2(o[j][0] * inv0, h0, lo0); split2(o[j][1] * inv0, h1, lo1);
        *(uint32_t*)(g_Oh + i0) = pack2(h0, h1);
        *(uint32_t*)(g_Ol + i0) = pack2(lo0, lo1);
        split2(o[j][2] * inv1, h0, lo0); split2(o[j][3] * inv1, h1, lo1);
        *(uint32_t*)(g_Oh + i1) = pack2(h0, h1);
        *(uint32_t*)(g_Ol + i1) = pack2(lo0, lo1);
    }
}

// ---------------- launch ------------------------------------------------------
extern "C" void kernel_launch(void* const* d_in, const int* in_sizes, int n_in,
                              void* d_out, int out_size)
{
    const float* x     = (const float*)d_in[0];
    const float* tx    = (const float*)d_in[1];
    const float* Wqkv  = (const float*)d_in[2];
    const float* Wtqkv = (const float*)d_in[3];
    const float* Wout  = (const float*)d_in[4];
    float* out = (float*)d_out;

    __nv_bfloat16 *pxh, *pxl, *ptxh, *ptxl, *pKh, *pKl, *pTQh, *pTQl, *pOh, *pOl;
    __nv_bfloat16 *pWkh, *pWkl, *pWvh, *pWvl, *pWtqh, *pWtql, *pWoh, *pWol;
    float *pV;
    cudaGetSymbolAddress((void**)&pxh,  g_xh);  cudaGetSymbolAddress((void**)&pxl,  g_xl);
    cudaGetSymbolAddress((void**)&ptxh, g_txh); cudaGetSymbolAddress((void**)&ptxl, g_txl);
    cudaGetSymbolAddress((void**)&pKh,  g_Kh);  cudaGetSymbolAddress((void**)&pKl,  g_Kl);
    cudaGetSymbolAddress((void**)&pTQh, g_TQh); cudaGetSymbolAddress((void**)&pTQl, g_TQl);
    cudaGetSymbolAddress((void**)&pOh,  g_Oh);  cudaGetSymbolAddress((void**)&pOl,  g_Ol);
    cudaGetSymbolAddress((void**)&pV,   g_V);
    cudaGetSymbolAddress((void**)&pWkh, g_Wkh); cudaGetSymbolAddress((void**)&pWkl, g_Wkl);
    cudaGetSymbolAddress((void**)&pWvh, g_Wvh); cudaGetSymbolAddress((void**)&pWvl, g_Wvl);
    cudaGetSymbolAddress((void**)&pWtqh,g_Wtqh);cudaGetSymbolAddress((void**)&pWtql,g_Wtql);
    cudaGetSymbolAddress((void**)&pWoh, g_Wouth);cudaGetSymbolAddress((void**)&pWol, g_Woutl);

    cudaFuncSetAttribute(gemm_proj<0>, cudaFuncAttributeMaxDynamicSharedMemorySize, 4 * STAGE_PROJ);
    cudaFuncSetAttribute(gemm_proj<1>, cudaFuncAttributeMaxDynamicSharedMemorySize, 4 * STAGE_PROJ);
    cudaFuncSetAttribute(flash_attn,   cudaFuncAttributeMaxDynamicSharedMemorySize, FSMEM);

    int nBig = MROWS * EMB, nW = EMB * EMB;
    split_convert<<<nBig/4/256, 256>>>(x,  pxh,  pxl,  nBig);
    split_convert<<<nBig/4/256, 256>>>(tx, ptxh, ptxl, nBig);
    split_convert<<<nW/4/256,   256>>>(Wout, pWoh, pWol, nW);
    permute_split_w<<<dim3(EMB/256, EMB), 256>>>(Wqkv, Wtqkv);

    dim3 pg(EMB/128, MROWS/128);   // (8, 32)
    gemm_proj<1><<<pg, 256, 4*STAGE_PROJ>>>(pxh,  pxl,  pWkh,  pWkl,  nullptr, pKh,  pKl);
    gemm_proj<0><<<pg, 256, 4*STAGE_PROJ>>>(pxh,  pxl,  pWvh,  pWvl,  pV,      nullptr, nullptr);
    gemm_proj<1><<<pg, 256, 4*STAGE_PROJ>>>(ptxh, ptxl, pWtqh, pWtql, nullptr, pTQh, pTQl);

    transpose_v<<<dim3(SEQ/32, DHEAD/32, NSLICE), dim3(32, 8)>>>();

    flash_attn<<<dim3(SEQ/128, NSLICE), 256, FSMEM>>>();

    gemm_proj<0><<<pg, 256, 4*STAGE_PROJ>>>(pOh, pOl, pWoh, pWol, out, nullptr, nullptr);
}

// round 5
// speedup vs baseline: 4.5047x; 1.0370x over previous
#include <cuda_runtime.h>
#include <cuda_bf16.h>
#include <math.h>
#include <stdint.h>

#define BATCH 2
#define SEQ   2048
#define EMB   1024
#define HEADS 16
#define DHEAD 64
#define MROWS (BATCH*SEQ)         // 4096
#define NSLICE (BATCH*HEADS)      // 32

// ---------------- scratch (static device globals; no allocation) -------------
__device__ __nv_bfloat16 g_xh [MROWS*EMB], g_xl [MROWS*EMB];
__device__ __nv_bfloat16 g_txh[MROWS*EMB], g_txl[MROWS*EMB];
__device__ __nv_bfloat16 g_Kh [MROWS*EMB], g_Kl [MROWS*EMB];
__device__ __nv_bfloat16 g_TQh[MROWS*EMB], g_TQl[MROWS*EMB];
__device__ float         g_V  [MROWS*EMB];
__device__ __nv_bfloat16 g_Vth[NSLICE*DHEAD*SEQ], g_Vtl[NSLICE*DHEAD*SEQ];
__device__ __nv_bfloat16 g_Oh [MROWS*EMB], g_Ol [MROWS*EMB];
__device__ __nv_bfloat16 g_Wkh [EMB*EMB], g_Wkl [EMB*EMB];
__device__ __nv_bfloat16 g_Wvh [EMB*EMB], g_Wvl [EMB*EMB];
__device__ __nv_bfloat16 g_Wtqh[EMB*EMB], g_Wtql[EMB*EMB];
__device__ __nv_bfloat16 g_Wouth[EMB*EMB], g_Woutl[EMB*EMB];

// ---------------- small helpers ----------------------------------------------
__device__ __forceinline__ uint32_t smem_u32(const void* p) {
    uint32_t a;
    asm("{ .reg .u64 t; cvta.to.shared.u64 t, %1; cvt.u32.u64 %0, t; }" : "=r"(a) : "l"(p));
    return a;
}
#define CP_ASYNC16(dst, src) \
    asm volatile("cp.async.cg.shared.global [%0], [%1], 16;" :: "r"(dst), "l"(src) : "memory")
#define CP_COMMIT() asm volatile("cp.async.commit_group;" ::: "memory")
#define CP_WAIT2()  asm volatile("cp.async.wait_group 2;" ::: "memory")
#define CP_WAIT1()  asm volatile("cp.async.wait_group 1;" ::: "memory")
#define CP_WAIT0()  asm volatile("cp.async.wait_group 0;" ::: "memory")

__device__ __forceinline__ void ldsm_x4(uint32_t r[4], uint32_t addr) {
    asm volatile("ldmatrix.sync.aligned.m8n8.x4.shared.b16 {%0,%1,%2,%3}, [%4];"
                 : "=r"(r[0]), "=r"(r[1]), "=r"(r[2]), "=r"(r[3]) : "r"(addr));
}
__device__ __forceinline__ void mma16816(float c[4], const uint32_t a[4],
                                         uint32_t b0, uint32_t b1) {
    asm volatile("mma.sync.aligned.m16n8k16.row.col.f32.bf16.bf16.f32 "
                 "{%0,%1,%2,%3},{%4,%5,%6,%7},{%8,%9},{%0,%1,%2,%3};"
                 : "+f"(c[0]), "+f"(c[1]), "+f"(c[2]), "+f"(c[3])
                 : "r"(a[0]), "r"(a[1]), "r"(a[2]), "r"(a[3]), "r"(b0), "r"(b1));
}
__device__ __forceinline__ uint32_t pack2(__nv_bfloat16 a, __nv_bfloat16 b) {
    return (uint32_t)__bfloat16_as_ushort(a) | ((uint32_t)__bfloat16_as_ushort(b) << 16);
}
__device__ __forceinline__ void split2(float x, __nv_bfloat16& h, __nv_bfloat16& l) {
    h = __float2bfloat16(x);
    l = __float2bfloat16(x - __bfloat162float(h));
}

// smem tile geometry
#define SSTR 80              // 32-half rows (projection GEMMs)
#define A_BYTES (128*SSTR)   // 10240
#define SSTR64 144           // 64-half rows (flash kernel), conflict-free
#define TILE_B (64*SSTR64)   // 9216

__device__ __forceinline__ void fill_rows(uint32_t dst, const __nv_bfloat16* src,
                                          int ld, int rows, int tid) {
    for (int j = tid; j < rows * 4; j += 256) {
        int r = j >> 2, cc = j & 3;
        CP_ASYNC16(dst + r * SSTR + cc * 16, src + (size_t)r * ld + cc * 8);
    }
}

template<int MT, int NP>
__device__ __forceinline__ void compute_stage(uint32_t abase, uint32_t bbase,
                                              int wrow, int wcol, int lane,
                                              float (*cfr)[4]) {
    const int arow  = wrow + (lane & 15);
    const int acolh = (lane >> 4) * 8;
    const int brow  = wcol + (lane & 7) + ((lane >> 4) << 3);
    const int bcolh = ((lane >> 3) & 1) * 8;
#pragma unroll
    for (int ks = 0; ks < 2; ks++) {
        uint32_t a[MT][4], b[NP][4];
#pragma unroll
        for (int mt = 0; mt < MT; mt++)
            ldsm_x4(a[mt], abase + (uint32_t)(arow + mt * 16) * SSTR + (acolh + ks * 16) * 2);
#pragma unroll
        for (int np = 0; np < NP; np++)
            ldsm_x4(b[np], bbase + (uint32_t)(brow + np * 16) * SSTR + (bcolh + ks * 16) * 2);
#pragma unroll
        for (int mt = 0; mt < MT; mt++)
#pragma unroll
            for (int np = 0; np < NP; np++) {
                mma16816(cfr[(mt * NP + np) * 2 + 0], a[mt], b[np][0], b[np][1]);
                mma16816(cfr[(mt * NP + np) * 2 + 1], a[mt], b[np][2], b[np][3]);
            }
    }
}

// ---------------- conversion kernels -----------------------------------------
__global__ void split_convert3(const float* __restrict__ X0, const float* __restrict__ X1,
                               const float* __restrict__ X2)
{
    int i = blockIdx.x * blockDim.x + threadIdx.x;
    const float* X; __nv_bfloat16 *H, *L;
    int nq = (MROWS * EMB) / 4;   // 1,048,576 per big array
    int wq = (EMB * EMB) / 4;     // 262,144 for Wout
    if (i < nq)               { X = X0; H = g_xh;  L = g_xl; }
    else if (i < 2 * nq)      { X = X1; H = g_txh; L = g_txl; i -= nq; }
    else if (i < 2 * nq + wq) { X = X2; H = g_Wouth; L = g_Woutl; i -= 2 * nq; }
    else return;
    float4 v = ((const float4*)X)[i];
    __nv_bfloat16 h0, h1, h2, h3, l0, l1, l2, l3;
    split2(v.x, h0, l0); split2(v.y, h1, l1);
    split2(v.z, h2, l2); split2(v.w, h3, l3);
    ((uint2*)H)[i] = make_uint2(pack2(h0, h1), pack2(h2, h3));
    ((uint2*)L)[i] = make_uint2(pack2(l0, l1), pack2(l2, l3));
}

__global__ void permute_split_w(const float* __restrict__ Wqkv,
                                const float* __restrict__ Wtqkv)
{
    int k = blockIdx.x * 256 + threadIdx.x;
    int n = blockIdx.y;
    int h = n >> 6, d = n & 63;
    size_t dst = (size_t)n * EMB + k;
    float vk  = Wqkv [(size_t)(d * 48 + 16 + h) * EMB + k];
    float vv  = Wqkv [(size_t)(d * 48 + 32 + h) * EMB + k];
    float vtq = Wtqkv[(size_t)(d * 48 +  0 + h) * EMB + k];
    __nv_bfloat16 hh, ll;
    split2(vk,  hh, ll); g_Wkh [dst] = hh; g_Wkl [dst] = ll;
    split2(vv,  hh, ll); g_Wvh [dst] = hh; g_Wvl [dst] = ll;
    split2(vtq, hh, ll); g_Wtqh[dst] = hh; g_Wtql[dst] = ll;
}

// ---------------- GEMM core (shared by merged-proj and output GEMM) ----------
#define PROJ_CHUNKS 96
#define STAGE_PROJ (A_BYTES + 128*SSTR)   // 20480

__device__ __forceinline__ void gemm_core(
    const __nv_bfloat16* Ah, const __nv_bfloat16* Al,
    const __nv_bfloat16* Bh, const __nv_bfloat16* Bl,
    int rowBase, int colBase, uint32_t sb, int tid, int lane,
    int wrow, int wcol, float (*cfr)[4])
{
#define PROJ_PTRS(c, ap, bp) {                                        \
        int term = (c) >> 5, k0 = ((c) & 31) << 5;                    \
        const __nv_bfloat16* As = (term < 2) ? Ah : Al;               \
        const __nv_bfloat16* Bs = (term == 1) ? Bl : Bh;              \
        ap = As + (size_t)rowBase * EMB + k0;                         \
        bp = Bs + (size_t)colBase * EMB + k0; }

    for (int c = 0; c < 3; c++) {
        const __nv_bfloat16 *ap, *bp; PROJ_PTRS(c, ap, bp);
        uint32_t st = sb + c * STAGE_PROJ;
        fill_rows(st, ap, EMB, 128, tid);
        fill_rows(st + A_BYTES, bp, EMB, 128, tid);
        CP_COMMIT();
    }
    for (int c = 0; c < PROJ_CHUNKS; c++) {
        CP_WAIT2();
        __syncthreads();
        if (c + 3 < PROJ_CHUNKS) {
            const __nv_bfloat16 *ap, *bp; PROJ_PTRS(c + 3, ap, bp);
            uint32_t st = sb + ((c + 3) & 3) * STAGE_PROJ;
            fill_rows(st, ap, EMB, 128, tid);
            fill_rows(st + A_BYTES, bp, EMB, 128, tid);
            CP_COMMIT();
        }
        uint32_t st = sb + (c & 3) * STAGE_PROJ;
        compute_stage<4, 2>(st, st + A_BYTES, wrow, wcol, lane, cfr);
    }
#undef PROJ_PTRS
}

// ---------------- merged projection GEMM (z: 0=K split, 1=V fp32, 2=TQ split)
__global__ void __launch_bounds__(256)
gemm_proj3()
{
    extern __shared__ char smem[];
    uint32_t sb = smem_u32(smem);
    const int tid = threadIdx.x, lane = tid & 31, warp = tid >> 5;
    const int rowBase = blockIdx.y * 128, colBase = blockIdx.x * 128;
    const int z = blockIdx.z;
    const int wrow = (warp >> 2) * 64, wcol = (warp & 3) * 32;

    const __nv_bfloat16 *Ah, *Al, *Bh, *Bl;
    if (z == 0)      { Ah = g_xh;  Al = g_xl;  Bh = g_Wkh;  Bl = g_Wkl;  }
    else if (z == 1) { Ah = g_xh;  Al = g_xl;  Bh = g_Wvh;  Bl = g_Wvl;  }
    else             { Ah = g_txh; Al = g_txl; Bh = g_Wtqh; Bl = g_Wtql; }

    float cfr[16][4];
#pragma unroll
    for (int i = 0; i < 16; i++)
#pragma unroll
        for (int j = 0; j < 4; j++) cfr[i][j] = 0.f;

    gemm_core(Ah, Al, Bh, Bl, rowBase, colBase, sb, tid, lane, wrow, wcol, cfr);

#pragma unroll
    for (int mt = 0; mt < 4; mt++)
#pragma unroll
        for (int np = 0; np < 2; np++)
#pragma unroll
            for (int t8 = 0; t8 < 2; t8++) {
                int nt = np * 2 + t8;
                int row = rowBase + wrow + mt * 16 + (lane >> 2);
                int col = colBase + wcol + nt * 8 + 2 * (lane & 3);
                float* cc = cfr[(mt * 2 + np) * 2 + t8];
#pragma unroll
                for (int half = 0; half < 2; half++) {
                    int r = row + half * 8;
                    float v0 = cc[half * 2], v1 = cc[half * 2 + 1];
                    if (z == 1) {
                        *(float2*)(g_V + (size_t)r * EMB + col) = make_float2(v0, v1);
                    } else {
                        __nv_bfloat16 h0, h1, l0, l1;
                        split2(v0, h0, l0); split2(v1, h1, l1);
                        __nv_bfloat16* H = (z == 0) ? g_Kh : g_TQh;
                        __nv_bfloat16* L = (z == 0) ? g_Kl : g_TQl;
                        *(uint32_t*)(H + (size_t)r * EMB + col) = pack2(h0, h1);
                        *(uint32_t*)(L + (size_t)r * EMB + col) = pack2(l0, l1);
                    }
                }
            }
}

// ---------------- output GEMM (fp32 out) -------------------------------------
__global__ void __launch_bounds__(256)
gemm_out(float* __restrict__ C)
{
    extern __shared__ char smem[];
    uint32_t sb = smem_u32(smem);
    const int tid = threadIdx.x, lane = tid & 31, warp = tid >> 5;
    const int rowBase = blockIdx.y * 128, colBase = blockIdx.x * 128;
    const int wrow = (warp >> 2) * 64, wcol = (warp & 3) * 32;

    float cfr[16][4];
#pragma unroll
    for (int i = 0; i < 16; i++)
#pragma unroll
        for (int j = 0; j < 4; j++) cfr[i][j] = 0.f;

    gemm_core(g_Oh, g_Ol, g_Wouth, g_Woutl, rowBase, colBase, sb, tid, lane, wrow, wcol, cfr);

#pragma unroll
    for (int mt = 0; mt < 4; mt++)
#pragma unroll
        for (int np = 0; np < 2; np++)
#pragma unroll
            for (int t8 = 0; t8 < 2; t8++) {
                int nt = np * 2 + t8;
                int row = rowBase + wrow + mt * 16 + (lane >> 2);
                int col = colBase + wcol + nt * 8 + 2 * (lane & 3);
                float* cc = cfr[(mt * 2 + np) * 2 + t8];
#pragma unroll
                for (int half = 0; half < 2; half++) {
                    int r = row + half * 8;
                    *(float2*)(C + (size_t)r * EMB + col) =
                        make_float2(cc[half * 2], cc[half * 2 + 1]);
                }
            }
}

// ---------------- V transpose: g_V fp32 -> Vt[z][d][t] bf16 split ------------
__global__ void transpose_v()
{
    __shared__ float tile[32][33];
    const int z = blockIdx.z, b = z >> 4, h = z & 15;
    const int t0 = blockIdx.x * 32, d0 = blockIdx.y * 32;
    const int tx = threadIdx.x, ty = threadIdx.y;   // (32, 8)
#pragma unroll
    for (int j = 0; j < 4; j++) {
        int t = t0 + ty + j * 8;
        tile[ty + j * 8][tx] = g_V[(size_t)(b * SEQ + t) * EMB + h * DHEAD + d0 + tx];
    }
    __syncthreads();
#pragma unroll
    for (int j = 0; j < 4; j++) {
        int d = d0 + ty + j * 8;
        float val = tile[tx][ty + j * 8];
        __nv_bfloat16 hh, ll;
        split2(val, hh, ll);
        size_t idx = ((size_t)z * DHEAD + d) * SEQ + t0 + tx;
        g_Vth[idx] = hh; g_Vtl[idx] = ll;
    }
}

// ---------------- fused flash attention (HMMA, 3-term split) -----------------
#define FSTAGE (4*TILE_B)    // 36864
#define FSMEM  (2*FSTAGE)    // 73728

__device__ __forceinline__ void fill_kv(uint32_t st, int t, int b, int h, int z, int tid)
{
    const size_t koff = (size_t)(b * SEQ + t * 64) * EMB + h * DHEAD;
    const size_t voff = (size_t)z * DHEAD * SEQ + t * 64;
    for (int j = tid; j < 64 * 8; j += 256) {
        int r = j >> 3, c = j & 7;
        uint32_t d = (uint32_t)r * SSTR64 + c * 16;
        size_t ko = koff + (size_t)r * EMB + c * 8;
        size_t vo = voff + (size_t)r * SEQ + c * 8;
        CP_ASYNC16(st + d,              g_Kh  + ko);
        CP_ASYNC16(st + TILE_B + d,     g_Kl  + ko);
        CP_ASYNC16(st + 2 * TILE_B + d, g_Vth + vo);
        CP_ASYNC16(st + 3 * TILE_B + d, g_Vtl + vo);
    }
}

__device__ __forceinline__ void qk_pass(uint32_t bbase, const uint32_t A[4][4],
                                        float (*s)[4], int lane)
{
    const int brow  = (lane & 7) + ((lane >> 4) << 3);
    const int bcolh = ((lane >> 3) & 1) * 8;
#pragma unroll
    for (int ks = 0; ks < 4; ks++) {
#pragma unroll
        for (int pr = 0; pr < 4; pr++) {
            uint32_t bf[4];
            ldsm_x4(bf, bbase + (uint32_t)(brow + pr * 16) * SSTR64 + (bcolh + ks * 16) * 2);
            mma16816(s[pr * 2 + 0], A[ks], bf[0], bf[1]);
            mma16816(s[pr * 2 + 1], A[ks], bf[2], bf[3]);
        }
    }
}

template<int LO>
__device__ __forceinline__ void pv_pass(uint32_t bbase, const float (*s)[4],
                                        float (*o)[4], int lane)
{
    const int brow  = (lane & 7) + ((lane >> 4) << 3);
    const int bcolh = ((lane >> 3) & 1) * 8;
#pragma unroll
    for (int ks = 0; ks < 4; ks++) {
        const float* c0 = s[2 * ks];
        const float* c1 = s[2 * ks + 1];
        uint32_t A[4];
        if (!LO) {
            A[0] = pack2(__float2bfloat16(c0[0]), __float2bfloat16(c0[1]));
            A[1] = pack2(__float2bfloat16(c0[2]), __float2bfloat16(c0[3]));
            A[2] = pack2(__float2bfloat16(c1[0]), __float2bfloat16(c1[1]));
            A[3] = pack2(__float2bfloat16(c1[2]), __float2bfloat16(c1[3]));
        } else {
            __nv_bfloat16 h, l;
#define RES(v) (split2((v), h, l), l)
            A[0] = pack2(RES(c0[0]), RES(c0[1]));
            A[1] = pack2(RES(c0[2]), RES(c0[3]));
            A[2] = pack2(RES(c1[0]), RES(c1[1]));
            A[3] = pack2(RES(c1[2]), RES(c1[3]));
#undef RES
        }
#pragma unroll
        for (int pr = 0; pr < 4; pr++) {
            uint32_t bf[4];
            ldsm_x4(bf, bbase + (uint32_t)(brow + pr * 16) * SSTR64 + (bcolh + ks * 16) * 2);
            mma16816(o[pr * 2 + 0], A, bf[0], bf[1]);
            mma16816(o[pr * 2 + 1], A, bf[2], bf[3]);
        }
    }
}

__global__ void __launch_bounds__(256, 2)
flash_attn()
{
    extern __shared__ char smem[];
    uint32_t sb = smem_u32(smem);
    const int tid = threadIdx.x, lane = tid & 31, warp = tid >> 5;
    const int rowBase = blockIdx.x * 128;
    const int z = blockIdx.y, b = z >> 4, h = z & 15;
    const int wrow = warp * 16;

    // ---- stage TQ (128 rows x 64 d, hi+lo) into stage0 area, hoist A-frags --
    {
        const size_t toff = (size_t)(b * SEQ + rowBase) * EMB + h * DHEAD;
        for (int j = tid; j < 128 * 8; j += 256) {
            int r = j >> 3, c = j & 7;
            uint32_t d = (uint32_t)r * SSTR64 + c * 16;
            size_t go = toff + (size_t)r * EMB + c * 8;
            CP_ASYNC16(sb + d,         g_TQh + go);
            CP_ASYNC16(sb + 18432 + d, g_TQl + go);
        }
        CP_COMMIT(); CP_WAIT0();
    }
    __syncthreads();

    uint32_t aqh[4][4], aql[4][4];
    {
        const int arow  = wrow + (lane & 15);
        const int acolh = (lane >> 4) * 8;
#pragma unroll
        for (int ks = 0; ks < 4; ks++) {
            ldsm_x4(aqh[ks], sb + (uint32_t)arow * SSTR64 + (acolh + ks * 16) * 2);
            ldsm_x4(aql[ks], sb + 18432 + (uint32_t)arow * SSTR64 + (acolh + ks * 16) * 2);
        }
    }
    __syncthreads();

    float o[8][4];
#pragma unroll
    for (int i = 0; i < 8; i++)
#pragma unroll
        for (int j = 0; j < 4; j++) o[i][j] = 0.f;
    float m0 = -INFINITY, m1 = -INFINITY, l0 = 0.f, l1 = 0.f;

    fill_kv(sb, 0, b, h, z, tid);
    CP_COMMIT();

    for (int t = 0; t < SEQ / 64; t++) {
        if (t + 1 < SEQ / 64) {
            fill_kv(sb + ((t + 1) & 1) * FSTAGE, t + 1, b, h, z, tid);
            CP_COMMIT();
            CP_WAIT1();
        } else {
            CP_WAIT0();
        }
        __syncthreads();
        uint32_t st = sb + (t & 1) * FSTAGE;

        float s[8][4];
#pragma unroll
        for (int i = 0; i < 8; i++)
#pragma unroll
            for (int j = 0; j < 4; j++) s[i][j] = 0.f;
        qk_pass(st,          aqh, s, lane);
        qk_pass(st + TILE_B, aqh, s, lane);
        qk_pass(st,          aql, s, lane);

        float rm0 = -INFINITY, rm1 = -INFINITY;
#pragma unroll
        for (int i = 0; i < 8; i++) {
            s[i][0] *= 8.f; s[i][1] *= 8.f; s[i][2] *= 8.f; s[i][3] *= 8.f;
            rm0 = fmaxf(rm0, fmaxf(s[i][0], s[i][1]));
            rm1 = fmaxf(rm1, fmaxf(s[i][2], s[i][3]));
        }
        rm0 = fmaxf(rm0, __shfl_xor_sync(0xffffffffu, rm0, 1));
        rm0 = fmaxf(rm0, __shfl_xor_sync(0xffffffffu, rm0, 2));
        rm1 = fmaxf(rm1, __shfl_xor_sync(0xffffffffu, rm1, 1));
        rm1 = fmaxf(rm1, __shfl_xor_sync(0xffffffffu, rm1, 2));
        float mn0 = fmaxf(m0, rm0), mn1 = fmaxf(m1, rm1);
        float c0 = __expf(m0 - mn0), c1 = __expf(m1 - mn1);
        l0 *= c0; l1 *= c1;
#pragma unroll
        for (int i = 0; i < 8; i++) {
            o[i][0] *= c0; o[i][1] *= c0; o[i][2] *= c1; o[i][3] *= c1;
            float p0 = __expf(s[i][0] - mn0), p1 = __expf(s[i][1] - mn0);
            float p2 = __expf(s[i][2] - mn1), p3 = __expf(s[i][3] - mn1);
            s[i][0] = p0; s[i][1] = p1; s[i][2] = p2; s[i][3] = p3;
            l0 += p0 + p1; l1 += p2 + p3;
        }
        m0 = mn0; m1 = mn1;

        pv_pass<0>(st + 2 * TILE_B, s, o, lane);
        pv_pass<1>(st + 2 * TILE_B, s, o, lane);
        pv_pass<0>(st + 3 * TILE_B, s, o, lane);
        __syncthreads();
    }

    l0 += __shfl_xor_sync(0xffffffffu, l0, 1);
    l0 += __shfl_xor_sync(0xffffffffu, l0, 2);
    l1 += __shfl_xor_sync(0xffffffffu, l1, 1);
    l1 += __shfl_xor_sync(0xffffffffu, l1, 2);
    float inv0 = 1.f / l0, inv1 = 1.f / l1;

    const int row0 = rowBase + wrow + (lane >> 2);
#pragma unroll
    for (int j = 0; j < 8; j++) {
        int col = h * DHEAD + j * 8 + 2 * (lane & 3);
        size_t i0 = (size_t)(b * SEQ + row0) * EMB + col;
        size_t i1 = (size_t)(b * SEQ + row0 + 8) * EMB + col;
        __nv_bfloat16 h0, h1, lo0, lo1;
        split2(o[j][0] * inv0, h0, lo0); split2(o[j][1] * inv0, h1, lo1);
        *(uint32_t*)(g_Oh + i0) = pack2(h0, h1);
        *(uint32_t*)(g_Ol + i0) = pack2(lo0, lo1);
        split2(o[j][2] * inv1, h0, lo0); split2(o[j][3] * inv1, h1, lo1);
        *(uint32_t*)(g_Oh + i1) = pack2(h0, h1);
        *(uint32_t*)(g_Ol + i1) = pack2(lo0, lo1);
    }
}

// ---------------- launch ------------------------------------------------------
extern "C" void kernel_launch(void* const* d_in, const int* in_sizes, int n_in,
                              void* d_out, int out_size)
{
    const float* x     = (const float*)d_in[0];
    const float* tx    = (const float*)d_in[1];
    const float* Wqkv  = (const float*)d_in[2];
    const float* Wtqkv = (const float*)d_in[3];
    const float* Wout  = (const float*)d_in[4];
    float* out = (float*)d_out;

    cudaFuncSetAttribute(gemm_proj3, cudaFuncAttributeMaxDynamicSharedMemorySize, 4 * STAGE_PROJ);
    cudaFuncSetAttribute(gemm_out,   cudaFuncAttributeMaxDynamicSharedMemorySize, 4 * STAGE_PROJ);
    cudaFuncSetAttribute(flash_attn, cudaFuncAttributeMaxDynamicSharedMemorySize, FSMEM);

    int totQ = 2 * (MROWS * EMB / 4) + (EMB * EMB / 4);   // 2.25M quads
    split_convert3<<<(totQ + 255) / 256, 256>>>(x, tx, Wout);
    permute_split_w<<<dim3(EMB/256, EMB), 256>>>(Wqkv, Wtqkv);

    gemm_proj3<<<dim3(EMB/128, MROWS/128, 3), 256, 4*STAGE_PROJ>>>();

    transpose_v<<<dim3(SEQ/32, DHEAD/32, NSLICE), dim3(32, 8)>>>();

    flash_attn<<<dim3(SEQ/128, NSLICE), 256, FSMEM>>>();

    gemm_out<<<dim3(EMB/128, MROWS/128), 256, 4*STAGE_PROJ>>>(out);
}